// round 12
// baseline (speedup 1.0000x reference)
#include <cuda_runtime.h>
#include <cuda_bf16.h>
#include <math.h>
#include <stdint.h>

// Problem constants (fixed by the reference)
#define NN 50000
#define EE 600000
#define DD 128
#define HH 4
#define INV_SCALE 0.17677669529663687f  // 1/sqrt(32)

// ---------------------------------------------------------------------------
// Scratch (device globals — no allocations allowed). All GEMM operands are
// pre-split fp32 -> (hi, lo) bf16 pairs so the GEMM mainloop does NO conversion.
// ---------------------------------------------------------------------------
__device__ __align__(16) __nv_bfloat16 g_Wqkv_h[3 * DD * DD];
__device__ __align__(16) __nv_bfloat16 g_Wqkv_l[3 * DD * DD];
__device__ __align__(16) __nv_bfloat16 g_We_h[DD * DD];
__device__ __align__(16) __nv_bfloat16 g_We_l[DD * DD];
__device__ __align__(16) __nv_bfloat16 g_Wn1_h[2 * DD * DD];
__device__ __align__(16) __nv_bfloat16 g_Wn1_l[2 * DD * DD];
__device__ __align__(16) __nv_bfloat16 g_Wn2_h[2 * DD * DD];
__device__ __align__(16) __nv_bfloat16 g_Wn2_l[2 * DD * DD];
__device__ __align__(16) __nv_bfloat16 g_We1_h[2 * DD * DD];
__device__ __align__(16) __nv_bfloat16 g_We1_l[2 * DD * DD];
__device__ __align__(16) __nv_bfloat16 g_We2_h[2 * DD * DD];
__device__ __align__(16) __nv_bfloat16 g_We2_l[2 * DD * DD];

__device__ __align__(16) __nv_bfloat16 g_nf_h[NN * DD];        // node_feats
__device__ __align__(16) __nv_bfloat16 g_nf_l[NN * DD];
__device__ __align__(16) __nv_bfloat16 g_ef_h[(size_t)EE * DD]; // edge_feats
__device__ __align__(16) __nv_bfloat16 g_ef_l[(size_t)EE * DD];

__device__ float g_QKV[(size_t)NN * 3 * DD];      // per node: [Q(128) K(128) V(128)] fp32
__device__ float g_wV[NN * DD];
__device__ float g_z[NN * HH];

__device__ __align__(16) __nv_bfloat16 g_score_h[(size_t)EE * DD];  // proj_e then score
__device__ __align__(16) __nv_bfloat16 g_score_l[(size_t)EE * DD];
__device__ __align__(16) __nv_bfloat16 g_h_h[NN * DD];
__device__ __align__(16) __nv_bfloat16 g_h_l[NN * DD];
__device__ __align__(16) __nv_bfloat16 g_hidn_h[NN * 2 * DD];
__device__ __align__(16) __nv_bfloat16 g_hidn_l[NN * 2 * DD];
__device__ __align__(16) __nv_bfloat16 g_hide_h[(size_t)EE * 2 * DD];
__device__ __align__(16) __nv_bfloat16 g_hide_l[(size_t)EE * 2 * DD];

__device__ __forceinline__ float silu_fast(float x) {
    return __fdividef(x, 1.0f + __expf(-x));
}

// hi/lo split helpers: x = hi + lo with hi = bf16(x)
__device__ __forceinline__ uint32_t pack_hi(float x0, float x1) {
    __nv_bfloat162 r = __floats2bfloat162_rn(x0, x1);
    return *(uint32_t*)&r;
}
__device__ __forceinline__ uint32_t pack_lo(float x0, float x1) {
    float h0 = __bfloat162float(__float2bfloat16(x0));
    float h1 = __bfloat162float(__float2bfloat16(x1));
    __nv_bfloat162 r = __floats2bfloat162_rn(x0 - h0, x1 - h1);
    return *(uint32_t*)&r;
}

// ---------------------------------------------------------------------------
// Streaming converters (run every replay; all graph-capturable)
// ---------------------------------------------------------------------------
__global__ void convert_hl(const float* __restrict__ src,
                           __nv_bfloat16* __restrict__ h,
                           __nv_bfloat16* __restrict__ l, int n4) {
    int i = blockIdx.x * blockDim.x + threadIdx.x;
    if (i >= n4) return;
    float4 v = ((const float4*)src)[i];
    uint2 hv = make_uint2(pack_hi(v.x, v.y), pack_hi(v.z, v.w));
    uint2 lv = make_uint2(pack_lo(v.x, v.y), pack_lo(v.z, v.w));
    ((uint2*)h)[i] = hv;
    ((uint2*)l)[i] = lv;
}

__global__ void pack_qkv_weights(const float* __restrict__ Wq,
                                 const float* __restrict__ Wk,
                                 const float* __restrict__ Wv) {
    int i = blockIdx.x * blockDim.x + threadIdx.x;
    if (i >= 3 * DD * DD / 4) return;
    const int per = DD * DD / 4;
    float4 v;
    if (i < per)            v = ((const float4*)Wq)[i];
    else if (i < 2 * per)   v = ((const float4*)Wk)[i - per];
    else                    v = ((const float4*)Wv)[i - 2 * per];
    ((uint2*)g_Wqkv_h)[i] = make_uint2(pack_hi(v.x, v.y), pack_hi(v.z, v.w));
    ((uint2*)g_Wqkv_l)[i] = make_uint2(pack_lo(v.x, v.y), pack_lo(v.z, v.w));
}

// ---------------------------------------------------------------------------
// Split-bf16 tensor-core GEMM over PRE-SPLIT operands:
//   C[m,n] = act( sum_k A[m,k] * W[n,k] ),  A ~ Ah+Al, W ~ Wh+Wl (bf16 pairs)
//   3 MMAs per product (hh + hl + lh), fp32 accum -> rel err ~1e-5.
//   BM=128, BN=64, BK=32, 256 threads, warp tile 32x32, register prefetch.
//   OUTPAIR=0: write fp32 C.  OUTPAIR=1: write (hi,lo) bf16 pair C.
// ---------------------------------------------------------------------------
#define MMA16816(acc, a0, a1, a2, a3, b0, b1)                               \
    asm("mma.sync.aligned.m16n8k16.row.col.f32.bf16.bf16.f32 "              \
        "{%0,%1,%2,%3}, {%4,%5,%6,%7}, {%8,%9}, {%0,%1,%2,%3};"             \
        : "+f"(acc[0]), "+f"(acc[1]), "+f"(acc[2]), "+f"(acc[3])            \
        : "r"(a0), "r"(a1), "r"(a2), "r"(a3), "r"(b0), "r"(b1))

template <int ACT, int OUTPAIR>
__global__ void __launch_bounds__(256, 2)
mma_gemm_nt(const __nv_bfloat16* __restrict__ Ah_g,
            const __nv_bfloat16* __restrict__ Al_g,
            const __nv_bfloat16* __restrict__ Wh_g,
            const __nv_bfloat16* __restrict__ Wl_g,
            float* __restrict__ Cf,
            __nv_bfloat16* __restrict__ Ch,
            __nv_bfloat16* __restrict__ Cl,
            int M, int N, int K) {
    constexpr int BM = 128, BN = 64, BK = 32;
    constexpr int LDT = 40;   // padded row stride in bf16 (conflict-free frag reads)

    __shared__ __nv_bfloat16 Ah[BM][LDT];
    __shared__ __nv_bfloat16 Al[BM][LDT];
    __shared__ __nv_bfloat16 Bh[BN][LDT];
    __shared__ __nv_bfloat16 Bl[BN][LDT];

    const int t    = threadIdx.x;
    const int lane = t & 31;
    const int warp = t >> 5;
    const int wm   = (warp >> 1) * 32;    // 0,32,64,96
    const int wn   = (warp & 1) * 32;     // 0,32
    const int g    = lane >> 2;           // 0..7
    const int tig  = lane & 3;            // 0..3

    const int m0 = blockIdx.x * BM;
    const int n0 = blockIdx.y * BN;

    // A loader: thread -> (row = t>>1, kbase = (t&1)*16); 2 uint4 (8 bf16 each) per buf
    const int ar = t >> 1;
    const int ak = (t & 1) * 16;
    // B loader: thread -> (row = t>>2, kbase = (t&3)*8); 1 uint4 per buf
    const int br = t >> 2;
    const int bk = (t & 3) * 8;

    const int   a_gm    = m0 + ar;
    const bool  a_valid = (a_gm < M);
    const __nv_bfloat16* a_src_h = Ah_g + (size_t)a_gm * K + ak;
    const __nv_bfloat16* a_src_l = Al_g + (size_t)a_gm * K + ak;
    const __nv_bfloat16* b_src_h = Wh_g + (size_t)(n0 + br) * K + bk;
    const __nv_bfloat16* b_src_l = Wl_g + (size_t)(n0 + br) * K + bk;

    float acc[2][4][4];
    #pragma unroll
    for (int mi = 0; mi < 2; mi++)
        #pragma unroll
        for (int ni = 0; ni < 4; ni++)
            #pragma unroll
            for (int r = 0; r < 4; r++) acc[mi][ni][r] = 0.f;

    const uint4 zero4 = make_uint4(0u, 0u, 0u, 0u);

    // prologue: fetch tile 0
    uint4 avh[2], avl[2], bvh, bvl;
    #pragma unroll
    for (int i = 0; i < 2; i++) {
        avh[i] = a_valid ? *(const uint4*)(a_src_h + i * 8) : zero4;
        avl[i] = a_valid ? *(const uint4*)(a_src_l + i * 8) : zero4;
    }
    bvh = *(const uint4*)(b_src_h);
    bvl = *(const uint4*)(b_src_l);

    for (int k0 = 0; k0 < K; k0 += BK) {
        // store staged tile to smem
        *(uint4*)&Ah[ar][ak]     = avh[0];
        *(uint4*)&Ah[ar][ak + 8] = avh[1];
        *(uint4*)&Al[ar][ak]     = avl[0];
        *(uint4*)&Al[ar][ak + 8] = avl[1];
        *(uint4*)&Bh[br][bk]     = bvh;
        *(uint4*)&Bl[br][bk]     = bvl;
        __syncthreads();

        // prefetch next tile (LDGs in flight through the MMA section)
        const int kn = k0 + BK;
        if (kn < K) {
            #pragma unroll
            for (int i = 0; i < 2; i++) {
                avh[i] = a_valid ? *(const uint4*)(a_src_h + kn + i * 8) : zero4;
                avl[i] = a_valid ? *(const uint4*)(a_src_l + kn + i * 8) : zero4;
            }
            bvh = *(const uint4*)(b_src_h + kn);
            bvl = *(const uint4*)(b_src_l + kn);
        }

        // MMA section
        #pragma unroll
        for (int ka = 0; ka < 2; ka++) {
            const int kb = ka * 16;
            uint32_t fah[2][4], fal[2][4];
            #pragma unroll
            for (int mi = 0; mi < 2; mi++) {
                int r0 = wm + mi * 16 + g;
                int c0 = kb + tig * 2;
                fah[mi][0] = *(const uint32_t*)&Ah[r0][c0];
                fah[mi][1] = *(const uint32_t*)&Ah[r0 + 8][c0];
                fah[mi][2] = *(const uint32_t*)&Ah[r0][c0 + 8];
                fah[mi][3] = *(const uint32_t*)&Ah[r0 + 8][c0 + 8];
                fal[mi][0] = *(const uint32_t*)&Al[r0][c0];
                fal[mi][1] = *(const uint32_t*)&Al[r0 + 8][c0];
                fal[mi][2] = *(const uint32_t*)&Al[r0][c0 + 8];
                fal[mi][3] = *(const uint32_t*)&Al[r0 + 8][c0 + 8];
            }
            #pragma unroll
            for (int ni = 0; ni < 4; ni++) {
                int nrow = wn + ni * 8 + g;
                int c0 = kb + tig * 2;
                uint32_t bh0 = *(const uint32_t*)&Bh[nrow][c0];
                uint32_t bh1 = *(const uint32_t*)&Bh[nrow][c0 + 8];
                uint32_t bl0 = *(const uint32_t*)&Bl[nrow][c0];
                uint32_t bl1 = *(const uint32_t*)&Bl[nrow][c0 + 8];
                #pragma unroll
                for (int mi = 0; mi < 2; mi++) {
                    MMA16816(acc[mi][ni], fah[mi][0], fah[mi][1], fah[mi][2], fah[mi][3], bh0, bh1);
                    MMA16816(acc[mi][ni], fah[mi][0], fah[mi][1], fah[mi][2], fah[mi][3], bl0, bl1);
                    MMA16816(acc[mi][ni], fal[mi][0], fal[mi][1], fal[mi][2], fal[mi][3], bh0, bh1);
                }
            }
        }
        __syncthreads();
    }

    // epilogue
    #pragma unroll
    for (int mi = 0; mi < 2; mi++) {
        #pragma unroll
        for (int ni = 0; ni < 4; ni++) {
            int gm0 = m0 + wm + mi * 16 + g;
            int col = n0 + wn + ni * 8 + tig * 2;
            float d0 = acc[mi][ni][0], d1 = acc[mi][ni][1];
            float d2 = acc[mi][ni][2], d3 = acc[mi][ni][3];
            if (ACT == 1) {
                d0 = silu_fast(d0); d1 = silu_fast(d1);
                d2 = silu_fast(d2); d3 = silu_fast(d3);
            }
            if (OUTPAIR) {
                if (gm0 < M) {
                    size_t o = (size_t)gm0 * N + col;
                    *(uint32_t*)(Ch + o) = pack_hi(d0, d1);
                    *(uint32_t*)(Cl + o) = pack_lo(d0, d1);
                }
                if (gm0 + 8 < M) {
                    size_t o = (size_t)(gm0 + 8) * N + col;
                    *(uint32_t*)(Ch + o) = pack_hi(d2, d3);
                    *(uint32_t*)(Cl + o) = pack_lo(d2, d3);
                }
            } else {
                if (gm0 < M)
                    *(float2*)(Cf + (size_t)gm0 * N + col) = make_float2(d0, d1);
                if (gm0 + 8 < M)
                    *(float2*)(Cf + (size_t)(gm0 + 8) * N + col) = make_float2(d2, d3);
            }
        }
    }
}

// ---------------------------------------------------------------------------
// Per-edge attention: one WARP per edge, lane handles 4 contiguous floats.
//   proj_e read from (hi,lo) pairs; score written back as (hi,lo) pairs.
// ---------------------------------------------------------------------------
__global__ void __launch_bounds__(256)
edge_attn_kernel(const int* __restrict__ src, const int* __restrict__ dst) {
    const int warp = threadIdx.x >> 5;
    const int lane = threadIdx.x & 31;
    const int e = blockIdx.x * 8 + warp;
    if (e >= EE) return;

    const int sn = __ldg(src + e);
    const int dn = __ldg(dst + e);
    const int base = lane * 4;              // 0..124; head = lane>>3

    const float* srow = g_QKV + (size_t)sn * (3 * DD);
    const float* drow = g_QKV + (size_t)dn * (3 * DD);

    float4 q4 = *(const float4*)(drow + base);              // Q[dst]
    float4 k4 = *(const float4*)(srow + DD + base);         // K[src]

    size_t so = (size_t)e * DD + base;
    uint2 ph = *(const uint2*)(g_score_h + so);
    uint2 pl = *(const uint2*)(g_score_l + so);
    float2 h0 = __bfloat1622float2(*(__nv_bfloat162*)&ph.x);
    float2 h1 = __bfloat1622float2(*(__nv_bfloat162*)&ph.y);
    float2 l0 = __bfloat1622float2(*(__nv_bfloat162*)&pl.x);
    float2 l1 = __bfloat1622float2(*(__nv_bfloat162*)&pl.y);
    float4 p4 = make_float4(h0.x + l0.x, h0.y + l0.y, h1.x + l1.x, h1.y + l1.y);

    float4 sc;
    sc.x = fminf(5.f, fmaxf(-5.f, k4.x * q4.x * INV_SCALE)) * p4.x;
    sc.y = fminf(5.f, fmaxf(-5.f, k4.y * q4.y * INV_SCALE)) * p4.y;
    sc.z = fminf(5.f, fmaxf(-5.f, k4.z * q4.z * INV_SCALE)) * p4.z;
    sc.w = fminf(5.f, fmaxf(-5.f, k4.w * q4.w * INV_SCALE)) * p4.w;

    *(uint2*)(g_score_h + so) = make_uint2(pack_hi(sc.x, sc.y), pack_hi(sc.z, sc.w));
    *(uint2*)(g_score_l + so) = make_uint2(pack_lo(sc.x, sc.y), pack_lo(sc.z, sc.w));

    // reduce 32 values per head: 4 in-thread + butterfly over the 8-lane group
    float sum = (sc.x + sc.y) + (sc.z + sc.w);
    #pragma unroll
    for (int off = 4; off > 0; off >>= 1)
        sum += __shfl_xor_sync(0xffffffffu, sum, off);

    float s = __expf(fminf(5.f, fmaxf(-5.f, sum)));

    float4 v4 = *(const float4*)(srow + 2 * DD + base);     // V[src]
    float4* wv = (float4*)(g_wV + (size_t)dn * DD + base);
    atomicAdd(wv, make_float4(v4.x * s, v4.y * s, v4.z * s, v4.w * s));
    if ((lane & 7) == 0) atomicAdd(&g_z[dn * HH + (lane >> 3)], s);
}

// ---------------------------------------------------------------------------
// h = wV / (z + 1e-6), written directly as (hi,lo) bf16 pairs
// ---------------------------------------------------------------------------
__global__ void divide_kernel() {
    int idx = blockIdx.x * blockDim.x + threadIdx.x;   // one 4-elem group per thread
    if (idx >= NN * DD / 4) return;
    int fbase = idx * 4;
    int n = fbase >> 7;
    int head = (fbase & 127) >> 5;
    float inv = __fdividef(1.0f, g_z[n * HH + head] + 1e-6f);
    float4 w = *(const float4*)(g_wV + fbase);
    w.x *= inv; w.y *= inv; w.z *= inv; w.w *= inv;
    ((uint2*)g_h_h)[idx] = make_uint2(pack_hi(w.x, w.y), pack_hi(w.z, w.w));
    ((uint2*)g_h_l)[idx] = make_uint2(pack_lo(w.x, w.y), pack_lo(w.z, w.w));
}

// ---------------------------------------------------------------------------
// kernel_launch
// inputs: 0 node_feats 1 edge_feats 2 src 3 dst 4 Wq 5 Wk 6 Wv 7 We
//         8 Wn1 9 Wn2 10 We1 11 We2
// output: [node_out (N*128) | edge_out (E*128)] fp32
// ---------------------------------------------------------------------------
extern "C" void kernel_launch(void* const* d_in, const int* in_sizes, int n_in,
                              void* d_out, int out_size) {
    const float* node_feats = (const float*)d_in[0];
    const float* edge_feats = (const float*)d_in[1];
    const int*   src        = (const int*)d_in[2];
    const int*   dst        = (const int*)d_in[3];
    const float* Wq  = (const float*)d_in[4];
    const float* Wk  = (const float*)d_in[5];
    const float* Wv  = (const float*)d_in[6];
    const float* We  = (const float*)d_in[7];
    const float* Wn1 = (const float*)d_in[8];
    const float* Wn2 = (const float*)d_in[9];
    const float* We1 = (const float*)d_in[10];
    const float* We2 = (const float*)d_in[11];

    float* node_out = (float*)d_out;
    float* edge_out = (float*)d_out + (size_t)NN * DD;

    __nv_bfloat16 *pWqkvH, *pWqkvL, *pWeH, *pWeL, *pWn1H, *pWn1L, *pWn2H, *pWn2L;
    __nv_bfloat16 *pWe1H, *pWe1L, *pWe2H, *pWe2L;
    __nv_bfloat16 *pNfH, *pNfL, *pEfH, *pEfL, *pScH, *pScL, *pHH, *pHL;
    __nv_bfloat16 *pHnH, *pHnL, *pHeH, *pHeL;
    float *pQKV, *pWV, *pZ;
    cudaGetSymbolAddress((void**)&pWqkvH, g_Wqkv_h);
    cudaGetSymbolAddress((void**)&pWqkvL, g_Wqkv_l);
    cudaGetSymbolAddress((void**)&pWeH,  g_We_h);
    cudaGetSymbolAddress((void**)&pWeL,  g_We_l);
    cudaGetSymbolAddress((void**)&pWn1H, g_Wn1_h);
    cudaGetSymbolAddress((void**)&pWn1L, g_Wn1_l);
    cudaGetSymbolAddress((void**)&pWn2H, g_Wn2_h);
    cudaGetSymbolAddress((void**)&pWn2L, g_Wn2_l);
    cudaGetSymbolAddress((void**)&pWe1H, g_We1_h);
    cudaGetSymbolAddress((void**)&pWe1L, g_We1_l);
    cudaGetSymbolAddress((void**)&pWe2H, g_We2_h);
    cudaGetSymbolAddress((void**)&pWe2L, g_We2_l);
    cudaGetSymbolAddress((void**)&pNfH,  g_nf_h);
    cudaGetSymbolAddress((void**)&pNfL,  g_nf_l);
    cudaGetSymbolAddress((void**)&pEfH,  g_ef_h);
    cudaGetSymbolAddress((void**)&pEfL,  g_ef_l);
    cudaGetSymbolAddress((void**)&pScH,  g_score_h);
    cudaGetSymbolAddress((void**)&pScL,  g_score_l);
    cudaGetSymbolAddress((void**)&pHH,   g_h_h);
    cudaGetSymbolAddress((void**)&pHL,   g_h_l);
    cudaGetSymbolAddress((void**)&pHnH,  g_hidn_h);
    cudaGetSymbolAddress((void**)&pHnL,  g_hidn_l);
    cudaGetSymbolAddress((void**)&pHeH,  g_hide_h);
    cudaGetSymbolAddress((void**)&pHeL,  g_hide_l);
    cudaGetSymbolAddress((void**)&pQKV,  g_QKV);
    cudaGetSymbolAddress((void**)&pWV,   g_wV);
    cudaGetSymbolAddress((void**)&pZ,    g_z);

    // 0) zero accumulators; split all GEMM operands to (hi,lo) bf16 pairs
    cudaMemsetAsync(pWV, 0, (size_t)NN * DD * sizeof(float));
    cudaMemsetAsync(pZ,  0, (size_t)NN * HH * sizeof(float));
    pack_qkv_weights<<<(3 * DD * DD / 4 + 255) / 256, 256>>>(Wq, Wk, Wv);
    convert_hl<<<(DD * DD / 4 + 255) / 256, 256>>>(We,  pWeH,  pWeL,  DD * DD / 4);
    convert_hl<<<(2 * DD * DD / 4 + 255) / 256, 256>>>(Wn1, pWn1H, pWn1L, 2 * DD * DD / 4);
    convert_hl<<<(2 * DD * DD / 4 + 255) / 256, 256>>>(Wn2, pWn2H, pWn2L, 2 * DD * DD / 4);
    convert_hl<<<(2 * DD * DD / 4 + 255) / 256, 256>>>(We1, pWe1H, pWe1L, 2 * DD * DD / 4);
    convert_hl<<<(2 * DD * DD / 4 + 255) / 256, 256>>>(We2, pWe2H, pWe2L, 2 * DD * DD / 4);
    convert_hl<<<(NN * DD / 4 + 255) / 256, 256>>>(node_feats, pNfH, pNfL, NN * DD / 4);
    convert_hl<<<((int)((size_t)EE * DD / 4) + 255) / 256, 256>>>(edge_feats, pEfH, pEfL, (int)((size_t)EE * DD / 4));

    // 1) QKV projection: [N,128] x [384,128]^T -> fp32 [N,384]
    {
        dim3 grid((NN + 127) / 128, (3 * DD) / 64);
        mma_gemm_nt<0, 0><<<grid, 256>>>(pNfH, pNfL, pWqkvH, pWqkvL, pQKV, nullptr, nullptr, NN, 3 * DD, DD);
    }

    // 2) proj_e = edge_feats @ We^T -> (hi,lo) pairs [E,128]
    {
        dim3 grid((EE + 127) / 128, DD / 64);
        mma_gemm_nt<0, 1><<<grid, 256>>>(pEfH, pEfL, pWeH, pWeL, nullptr, pScH, pScL, EE, DD, DD);
    }

    // 3) per-edge attention + scatter (8 warps/block, 1 edge/warp)
    edge_attn_kernel<<<(EE + 7) / 8, 256>>>(src, dst);

    // 4) h = wV / (z + eps) -> (hi,lo) pairs
    divide_kernel<<<(NN * DD / 4 + 255) / 256, 256>>>();

    // 5) node MLP: silu(h @ Wn1^T) @ Wn2^T
    {
        dim3 g1((NN + 127) / 128, (2 * DD) / 64);
        mma_gemm_nt<1, 1><<<g1, 256>>>(pHH, pHL, pWn1H, pWn1L, nullptr, pHnH, pHnL, NN, 2 * DD, DD);
        dim3 g2((NN + 127) / 128, DD / 64);
        mma_gemm_nt<0, 0><<<g2, 256>>>(pHnH, pHnL, pWn2H, pWn2L, node_out, nullptr, nullptr, NN, DD, 2 * DD);
    }

    // 6) edge MLP: silu(score @ We1^T) @ We2^T
    {
        dim3 g1((EE + 127) / 128, (2 * DD) / 64);
        mma_gemm_nt<1, 1><<<g1, 256>>>(pScH, pScL, pWe1H, pWe1L, nullptr, pHeH, pHeL, EE, 2 * DD, DD);
        dim3 g2((EE + 127) / 128, DD / 64);
        mma_gemm_nt<0, 0><<<g2, 256>>>(pHeH, pHeL, pWe2H, pWe2L, edge_out, nullptr, nullptr, EE, DD, 2 * DD);
    }
}